// round 2
// baseline (speedup 1.0000x reference)
#include <cuda_runtime.h>
#include <math.h>

#define NN 16384
#define DD 512
#define OO 512
#define MINN 1e-15f

#define BM 128
#define BN 128
#define BK 16

// Scratch for precomputed per-row stats (no allocations allowed).
__device__ float g_x2[NN];
__device__ float g_p2[OO];
__device__ float g_pa[OO];
__device__ float g_anorm[OO];
__device__ float g_escale[OO];

__device__ __forceinline__ float warp_sum(float v) {
#pragma unroll
    for (int s = 16; s > 0; s >>= 1) v += __shfl_xor_sync(0xffffffffu, v, s);
    return v;
}

// ---------------- per-O stats: ||p||^2, <p,a>, ||a||, exp(scale) ----------------
__global__ void stats_o(const float* __restrict__ P, const float* __restrict__ A,
                        const float* __restrict__ S) {
    int o = blockIdx.x;
    int t = threadIdx.x;  // 128 threads, DD/4 = 128 float4 per row
    const float4* p4 = reinterpret_cast<const float4*>(P + (size_t)o * DD);
    const float4* a4 = reinterpret_cast<const float4*>(A + (size_t)o * DD);
    float4 pv = p4[t], av = a4[t];
    float sp2 = pv.x * pv.x + pv.y * pv.y + pv.z * pv.z + pv.w * pv.w;
    float spa = pv.x * av.x + pv.y * av.y + pv.z * av.z + pv.w * av.w;
    float sa2 = av.x * av.x + av.y * av.y + av.z * av.z + av.w * av.w;
    sp2 = warp_sum(sp2);
    spa = warp_sum(spa);
    sa2 = warp_sum(sa2);
    __shared__ float sm[3][4];
    int w = t >> 5, l = t & 31;
    if (l == 0) { sm[0][w] = sp2; sm[1][w] = spa; sm[2][w] = sa2; }
    __syncthreads();
    if (t == 0) {
        float tp2 = sm[0][0] + sm[0][1] + sm[0][2] + sm[0][3];
        float tpa = sm[1][0] + sm[1][1] + sm[1][2] + sm[1][3];
        float ta2 = sm[2][0] + sm[2][1] + sm[2][2] + sm[2][3];
        g_p2[o] = tp2;
        g_pa[o] = tpa;
        g_anorm[o] = fmaxf(sqrtf(ta2), MINN);
        g_escale[o] = expf(S[o]);
    }
}

// ---------------- per-row ||x||^2 (one warp per row) ----------------
__global__ void stats_x(const float* __restrict__ X) {
    int warp = (blockIdx.x * blockDim.x + threadIdx.x) >> 5;
    int lane = threadIdx.x & 31;
    if (warp >= NN) return;
    const float4* x4 = reinterpret_cast<const float4*>(X + (size_t)warp * DD);
    float s = 0.f;
#pragma unroll
    for (int j = 0; j < 4; j++) {
        float4 v = x4[lane + 32 * j];
        s += v.x * v.x + v.y * v.y + v.z * v.z + v.w * v.w;
    }
    s = warp_sum(s);
    if (lane == 0) g_x2[warp] = s;
}

// ---------------- packed f32x2 helpers (FFMA2 path, PTX-only) ----------------
typedef unsigned long long u64;

__device__ __forceinline__ u64 pk2(float lo, float hi) {
    u64 r;
    asm("mov.b64 %0, {%1, %2};" : "=l"(r) : "f"(lo), "f"(hi));
    return r;
}
__device__ __forceinline__ void fma2(u64& d, u64 a, u64 b) {
    asm("fma.rn.f32x2 %0, %1, %2, %0;" : "+l"(d) : "l"(a), "l"(b));
}
__device__ __forceinline__ float2 upk2(u64 v) {
    float2 r;
    asm("mov.b64 {%0, %1}, %2;" : "=f"(r.x), "=f"(r.y) : "l"(v));
    return r;
}

// ---------------- main fused dual-GEMM + Mobius epilogue ----------------
// 128x128 block tile, 256 threads, 8x8 microtile (4+4 split on both axes).
__global__ __launch_bounds__(256, 1) void mobius_main(
    const float* __restrict__ X, const float* __restrict__ P,
    const float* __restrict__ A, float* __restrict__ out) {
    __shared__ float xs[BK][BM + 4];
    __shared__ float ps[BK][BN + 4];
    __shared__ float as_[BK][BN + 4];

    int tid = threadIdx.x;
    int tx = tid & 15, ty = tid >> 4;   // 16x16 thread grid
    int m0 = blockIdx.y * BM, n0 = blockIdx.x * BN;
    int lr = tid >> 1;                  // load row 0..127
    int lk = (tid & 1) << 3;            // k offset 0 or 8

    const float* xg = X + (size_t)(m0 + lr) * DD + lk;
    const float* pg = P + (size_t)(n0 + lr) * DD + lk;
    const float* ag = A + (size_t)(n0 + lr) * DD + lk;

    u64 accP[8][4];   // [m(8)][n-pair(4)]: pairs (clo,clo+1)(clo+2,clo+3)(chi..)(chi..)
    u64 accA[8][4];
#pragma unroll
    for (int i = 0; i < 8; i++)
#pragma unroll
        for (int j = 0; j < 4; j++) { accP[i][j] = 0ull; accA[i][j] = 0ull; }

    // prefetch first tile
    float4 xv0 = *reinterpret_cast<const float4*>(xg);
    float4 xv1 = *reinterpret_cast<const float4*>(xg + 4);
    float4 pv0 = *reinterpret_cast<const float4*>(pg);
    float4 pv1 = *reinterpret_cast<const float4*>(pg + 4);
    float4 av0 = *reinterpret_cast<const float4*>(ag);
    float4 av1 = *reinterpret_cast<const float4*>(ag + 4);

    for (int k0 = 0; k0 < DD; k0 += BK) {
        if (k0) __syncthreads();
        xs[lk + 0][lr] = xv0.x; xs[lk + 1][lr] = xv0.y;
        xs[lk + 2][lr] = xv0.z; xs[lk + 3][lr] = xv0.w;
        xs[lk + 4][lr] = xv1.x; xs[lk + 5][lr] = xv1.y;
        xs[lk + 6][lr] = xv1.z; xs[lk + 7][lr] = xv1.w;
        ps[lk + 0][lr] = pv0.x; ps[lk + 1][lr] = pv0.y;
        ps[lk + 2][lr] = pv0.z; ps[lk + 3][lr] = pv0.w;
        ps[lk + 4][lr] = pv1.x; ps[lk + 5][lr] = pv1.y;
        ps[lk + 6][lr] = pv1.z; ps[lk + 7][lr] = pv1.w;
        as_[lk + 0][lr] = av0.x; as_[lk + 1][lr] = av0.y;
        as_[lk + 2][lr] = av0.z; as_[lk + 3][lr] = av0.w;
        as_[lk + 4][lr] = av1.x; as_[lk + 5][lr] = av1.y;
        as_[lk + 6][lr] = av1.z; as_[lk + 7][lr] = av1.w;
        __syncthreads();

        // prefetch next tile (hidden behind compute)
        if (k0 + BK < DD) {
            xv0 = *reinterpret_cast<const float4*>(xg + k0 + BK);
            xv1 = *reinterpret_cast<const float4*>(xg + k0 + BK + 4);
            pv0 = *reinterpret_cast<const float4*>(pg + k0 + BK);
            pv1 = *reinterpret_cast<const float4*>(pg + k0 + BK + 4);
            av0 = *reinterpret_cast<const float4*>(ag + k0 + BK);
            av1 = *reinterpret_cast<const float4*>(ag + k0 + BK + 4);
        }

#pragma unroll
        for (int k = 0; k < BK; k++) {
            float4 xlo = *reinterpret_cast<const float4*>(&xs[k][ty << 2]);
            float4 xhi = *reinterpret_cast<const float4*>(&xs[k][64 + (ty << 2)]);
            float4 plo = *reinterpret_cast<const float4*>(&ps[k][tx << 2]);
            float4 phi = *reinterpret_cast<const float4*>(&ps[k][64 + (tx << 2)]);
            float4 alo = *reinterpret_cast<const float4*>(&as_[k][tx << 2]);
            float4 ahi = *reinterpret_cast<const float4*>(&as_[k][64 + (tx << 2)]);
            u64 pp[4] = {pk2(plo.x, plo.y), pk2(plo.z, plo.w),
                         pk2(phi.x, phi.y), pk2(phi.z, phi.w)};
            u64 aa[4] = {pk2(alo.x, alo.y), pk2(alo.z, alo.w),
                         pk2(ahi.x, ahi.y), pk2(ahi.z, ahi.w)};
            float xv[8] = {xlo.x, xlo.y, xlo.z, xlo.w,
                           xhi.x, xhi.y, xhi.z, xhi.w};
#pragma unroll
            for (int i = 0; i < 8; i++) {
                u64 xd = pk2(xv[i], xv[i]);
#pragma unroll
                for (int j = 0; j < 4; j++) {
                    fma2(accP[i][j], xd, pp[j]);
                    fma2(accA[i][j], xd, aa[j]);
                }
            }
        }
    }

    // ---- epilogue: Mobius dist2plane (c = 1, sqrt_c = 1) ----
    int clo = n0 + (tx << 2);
    int chi = clo + 64;
    float p2c[8], pac[8], anc[8], esc[8];
#pragma unroll
    for (int j = 0; j < 8; j++) {
        int col = (j < 4) ? (clo + j) : (chi + j - 4);
        p2c[j] = g_p2[col];
        pac[j] = g_pa[col];
        anc[j] = g_anorm[col];
        esc[j] = g_escale[col];
    }
#pragma unroll
    for (int i = 0; i < 8; i++) {
        int row = m0 + ((i < 4) ? ((ty << 2) + i) : (64 + (ty << 2) + i - 4));
        float x2 = g_x2[row];
        float xpv[8], xav[8];
#pragma unroll
        for (int j = 0; j < 4; j++) {
            float2 vP = upk2(accP[i][j]);
            float2 vA = upk2(accA[i][j]);
            xpv[2 * j] = vP.x; xpv[2 * j + 1] = vP.y;
            xav[2 * j] = vA.x; xav[2 * j + 1] = vA.y;
        }
        float res[8];
#pragma unroll
        for (int j = 0; j < 8; j++) {
            float xp = xpv[j], xa = xav[j];
            float Ac = 1.f - 2.f * xp + x2;          // A = 1 + 2c<x,-p> + c||x||^2
            float B = 1.f - p2c[j];                  // B = 1 - c||p||^2
            float Dn = fmaxf(1.f - 2.f * xp + p2c[j] * x2, MINN);
            float dn2 = Ac * Ac * p2c[j] - 2.f * Ac * B * xp + B * B * x2;
            float dnorm2 = fmaxf(dn2 / (Dn * Dn), MINN);
            float sc = (-Ac * pac[j] + B * xa) / Dn; // <diff, a>
            float denom = fmaxf((1.f - dnorm2) * anc[j], MINN);
            res[j] = asinhf(2.f * sc / denom) * esc[j];
        }
        float* orow = out + (size_t)row * OO;
        *reinterpret_cast<float4*>(orow + clo) =
            make_float4(res[0], res[1], res[2], res[3]);
        *reinterpret_cast<float4*>(orow + chi) =
            make_float4(res[4], res[5], res[6], res[7]);
    }
}

extern "C" void kernel_launch(void* const* d_in, const int* in_sizes, int n_in,
                              void* d_out, int out_size) {
    const float* x = (const float*)d_in[0];      // [N, D]
    const float* p = (const float*)d_in[1];      // [O, D]
    const float* a = (const float*)d_in[2];      // [O, D]
    const float* s = (const float*)d_in[3];      // [O]
    float* out = (float*)d_out;                  // [N, O]

    stats_o<<<OO, 128>>>(p, a, s);
    stats_x<<<(NN * 32) / 256, 256>>>(x);
    dim3 grid(OO / BN, NN / BM);
    mobius_main<<<grid, 256>>>(x, p, a, out);
}

// round 4
// speedup vs baseline: 3.9296x; 3.9296x over previous
#include <cuda_runtime.h>
#include <math.h>
#include <cstdint>

#define NN 16384
#define DD 512
#define OO 512
#define BM 128
#define BN 128
#define BK 32
#define NKT (DD / BK)          // 16 k-tiles
#define LSTR 36                // smem floats per row (BK + 4) -> conflict-free frags
#define TILE_F (BM * LSTR)     // 4608 floats per matrix tile
#define STAGE_F (3 * TILE_F)   // X + P + A
#define SMEM_BYTES (3 * STAGE_F * 4)  // 165888 B, 3 stages
#define MINN 1e-15f

// Precomputed stats (no allocations allowed -> device globals).
__device__ float g_a0[NN];   // 1 + ||x||^2
__device__ float g_rr[NN];   // 2 / (1 - ||x||^2)
__device__ float g_B[OO];    // 1 - ||p||^2   (fp64-accurate)
__device__ float g_pa[OO];   // <p, a>
__device__ float g_q[OO];    // 1 / (B * ||a||)
__device__ float g_e2[OO];   // ln(2) * exp(scale)

__device__ __forceinline__ float warp_sum(float v) {
#pragma unroll
    for (int s = 16; s > 0; s >>= 1) v += __shfl_xor_sync(0xffffffffu, v, s);
    return v;
}
__device__ __forceinline__ double warp_sum_d(double v) {
#pragma unroll
    for (int s = 16; s > 0; s >>= 1) v += __shfl_xor_sync(0xffffffffu, v, s);
    return v;
}

// ---------------- per-O stats ----------------
__global__ void stats_o(const float* __restrict__ P, const float* __restrict__ A,
                        const float* __restrict__ S) {
    int w = threadIdx.x >> 5, lane = threadIdx.x & 31;
    int o = blockIdx.x * 32 + w;
    const float4* p4 = reinterpret_cast<const float4*>(P + (size_t)o * DD);
    const float4* a4 = reinterpret_cast<const float4*>(A + (size_t)o * DD);
    double p2 = 0.0;
    float pa = 0.f, a2 = 0.f;
#pragma unroll
    for (int j = 0; j < 4; j++) {
        float4 pv = p4[lane + 32 * j];
        float4 av = a4[lane + 32 * j];
        p2 += (double)pv.x * pv.x + (double)pv.y * pv.y +
              (double)pv.z * pv.z + (double)pv.w * pv.w;
        pa += pv.x * av.x + pv.y * av.y + pv.z * av.z + pv.w * av.w;
        a2 += av.x * av.x + av.y * av.y + av.z * av.z + av.w * av.w;
    }
    p2 = warp_sum_d(p2);
    pa = warp_sum(pa);
    a2 = warp_sum(a2);
    if (lane == 0) {
        double B = 1.0 - p2;   // catastrophic cancellation handled in fp64
        double an = sqrt((double)a2);
        if (an < (double)MINN) an = (double)MINN;
        g_B[o] = (float)B;
        g_pa[o] = pa;
        g_q[o] = (float)(1.0 / (B * an));
        g_e2[o] = 0.69314718055994530942f * expf(S[o]);
    }
}

// ---------------- per-row ||x||^2 -> a0, rr ----------------
__global__ void stats_x(const float* __restrict__ X) {
    int warp = (blockIdx.x * blockDim.x + threadIdx.x) >> 5;
    int lane = threadIdx.x & 31;
    const float4* x4 = reinterpret_cast<const float4*>(X + (size_t)warp * DD);
    float s = 0.f;
#pragma unroll
    for (int j = 0; j < 4; j++) {
        float4 v = x4[lane + 32 * j];
        s += v.x * v.x + v.y * v.y + v.z * v.z + v.w * v.w;
    }
    s = warp_sum(s);
    if (lane == 0) {
        g_a0[warp] = 1.f + s;
        g_rr[warp] = 2.f / (1.f - s);
    }
}

// ---------------- PTX helpers ----------------
__device__ __forceinline__ uint32_t cvt_tf32(float x) {
    uint32_t r;
    asm("cvt.rna.tf32.f32 %0, %1;" : "=r"(r) : "f"(x));
    return r;
}

#define MMA_TF32(d, a, b0, b1)                                                 \
    asm volatile(                                                              \
        "mma.sync.aligned.m16n8k8.row.col.f32.tf32.tf32.f32 "                  \
        "{%0,%1,%2,%3}, {%4,%5,%6,%7}, {%8,%9}, {%0,%1,%2,%3};"                \
        : "+f"((d)[0]), "+f"((d)[1]), "+f"((d)[2]), "+f"((d)[3])               \
        : "r"((a)[0]), "r"((a)[1]), "r"((a)[2]), "r"((a)[3]), "r"(b0), "r"(b1))

#define CPA16(saddr, gptr)                                                     \
    asm volatile("cp.async.cg.shared.global [%0], [%1], 16;"                   \
                 :: "r"(saddr), "l"(gptr))
#define CPA_COMMIT() asm volatile("cp.async.commit_group;" ::: "memory")
#define CPA_WAIT1() asm volatile("cp.async.wait_group 1;" ::: "memory")

// asinh(arg) * e2/ln2 via fast MUFU path: ln(t + sqrt(t^2+1)) = lg2(.)*ln2
__device__ __forceinline__ float epi(float xp, float xa, float a0, float rr,
                                     float B, float pa, float q, float e2) {
    float Aa = fmaf(-2.f, xp, a0);      // A = 1 + x^2 - 2*xp
    float tn = fmaf(B, xa, -Aa * pa);   // B*xa - A*pa
    float arg = tn * rr * q;            // 2*tn / (B*(1-x^2)*||a||)
    float tt = fabsf(arg);
    float s;
    asm("sqrt.approx.f32 %0, %1;" : "=f"(s) : "f"(fmaf(tt, tt, 1.f)));
    float u = tt + s;
    float r;
    asm("lg2.approx.f32 %0, %1;" : "=f"(r) : "f"(u));
    return copysignf(r * e2, arg);
}

// ---------------- main: tf32 mma.sync dual-GEMM + analytic Mobius epilogue ----
__global__ void __launch_bounds__(256, 1) mobius_main(
    const float* __restrict__ X, const float* __restrict__ P,
    const float* __restrict__ A, float* __restrict__ out) {
    extern __shared__ float sm[];
    int tid = threadIdx.x;
    int lane = tid & 31, wid = tid >> 5;
    int wm = wid & 1, wn = wid >> 1;        // 2 x 4 warp grid, warp tile 64x32
    int m0 = blockIdx.y * BM, n0 = blockIdx.x * BN;

    const float* Xg = X + (size_t)m0 * DD;
    const float* Pg = P + (size_t)n0 * DD;
    const float* Ag = A + (size_t)n0 * DD;
    uint32_t sbase = (uint32_t)__cvta_generic_to_shared(sm);

    // per-thread cp.async mapping: 4 float4 per matrix per stage
    int f_row[4], f_c4[4];
#pragma unroll
    for (int j = 0; j < 4; j++) {
        int f = tid + 256 * j;          // 0..1023
        f_row[j] = f >> 3;
        f_c4[j] = (f & 7) << 2;
    }

#define LOAD_STAGE(stg, kt)                                                    \
    {                                                                          \
        uint32_t st = sbase + (uint32_t)(stg) * (STAGE_F * 4);                 \
        int k0 = (kt) * BK;                                                    \
        _Pragma("unroll") for (int j = 0; j < 4; j++) {                        \
            uint32_t so = st + (uint32_t)(f_row[j] * LSTR + f_c4[j]) * 4;      \
            size_t go = (size_t)f_row[j] * DD + k0 + f_c4[j];                  \
            CPA16(so, Xg + go);                                                \
            CPA16(so + TILE_F * 4, Pg + go);                                   \
            CPA16(so + 2 * TILE_F * 4, Ag + go);                               \
        }                                                                      \
    }

    float accP[4][4][4];
    float accA[4][4][4];
#pragma unroll
    for (int mt = 0; mt < 4; mt++)
#pragma unroll
        for (int nt = 0; nt < 4; nt++)
#pragma unroll
            for (int e = 0; e < 4; e++) { accP[mt][nt][e] = 0.f; accA[mt][nt][e] = 0.f; }

    LOAD_STAGE(0, 0); CPA_COMMIT();
    LOAD_STAGE(1, 1); CPA_COMMIT();

    int g = lane >> 2, t = lane & 3;
    // fragment base offsets (floats) within a stage
    int x_off = (wm * 64 + g) * LSTR + t;   // A-frag base (x tile)
    int b_off = (wn * 32 + g) * LSTR + t;   // B-frag base (p/a tiles; row = n)

    for (int c = 0; c < NKT; ++c) {
        CPA_WAIT1();
        __syncthreads();
        if (c + 2 < NKT) { LOAD_STAGE((c + 2) % 3, c + 2); }
        CPA_COMMIT();

        const float* Xs = sm + (c % 3) * STAGE_F;
        const float* Ps = Xs + TILE_F;
        const float* As = Ps + TILE_F;
#pragma unroll
        for (int ks = 0; ks < 4; ks++) {
            uint32_t af[4][4];
#pragma unroll
            for (int mt = 0; mt < 4; mt++) {
                const float* xb = Xs + x_off + mt * 16 * LSTR + ks * 8;
                af[mt][0] = cvt_tf32(xb[0]);
                af[mt][1] = cvt_tf32(xb[8 * LSTR]);
                af[mt][2] = cvt_tf32(xb[4]);
                af[mt][3] = cvt_tf32(xb[8 * LSTR + 4]);
            }
#pragma unroll
            for (int nt = 0; nt < 4; nt++) {
                const float* pb = Ps + b_off + nt * 8 * LSTR + ks * 8;
                const float* ab = As + b_off + nt * 8 * LSTR + ks * 8;
                uint32_t bp0 = cvt_tf32(pb[0]), bp1 = cvt_tf32(pb[4]);
                uint32_t ba0 = cvt_tf32(ab[0]), ba1 = cvt_tf32(ab[4]);
#pragma unroll
                for (int mt = 0; mt < 4; mt++) {
                    MMA_TF32(accP[mt][nt], af[mt], bp0, bp1);
                    MMA_TF32(accA[mt][nt], af[mt], ba0, ba1);
                }
            }
        }
    }

    // ---- epilogue ----
    float a0r[4][2], rrr[4][2];
#pragma unroll
    for (int mt = 0; mt < 4; mt++)
#pragma unroll
        for (int h = 0; h < 2; h++) {
            int r = m0 + wm * 64 + mt * 16 + g + h * 8;
            a0r[mt][h] = g_a0[r];
            rrr[mt][h] = g_rr[r];
        }
    float Bc[4][2], pac[4][2], qc[4][2], e2c[4][2];
#pragma unroll
    for (int nt = 0; nt < 4; nt++)
#pragma unroll
        for (int w = 0; w < 2; w++) {
            int cc = n0 + wn * 32 + nt * 8 + 2 * t + w;
            Bc[nt][w] = g_B[cc];
            pac[nt][w] = g_pa[cc];
            qc[nt][w] = g_q[cc];
            e2c[nt][w] = g_e2[cc];
        }
#pragma unroll
    for (int mt = 0; mt < 4; mt++) {
#pragma unroll
        for (int h = 0; h < 2; h++) {
            int r = m0 + wm * 64 + mt * 16 + g + h * 8;
            float* orow = out + (size_t)r * OO + n0 + wn * 32 + 2 * t;
#pragma unroll
            for (int nt = 0; nt < 4; nt++) {
                float o0 = epi(accP[mt][nt][h * 2 + 0], accA[mt][nt][h * 2 + 0],
                               a0r[mt][h], rrr[mt][h],
                               Bc[nt][0], pac[nt][0], qc[nt][0], e2c[nt][0]);
                float o1 = epi(accP[mt][nt][h * 2 + 1], accA[mt][nt][h * 2 + 1],
                               a0r[mt][h], rrr[mt][h],
                               Bc[nt][1], pac[nt][1], qc[nt][1], e2c[nt][1]);
                *reinterpret_cast<float2*>(orow + nt * 8) = make_float2(o0, o1);
            }
        }
    }
}

extern "C" void kernel_launch(void* const* d_in, const int* in_sizes, int n_in,
                              void* d_out, int out_size) {
    const float* x = (const float*)d_in[0];      // [N, D]
    const float* p = (const float*)d_in[1];      // [O, D]
    const float* a = (const float*)d_in[2];      // [O, D]
    const float* s = (const float*)d_in[3];      // [O]
    float* out = (float*)d_out;                  // [N, O]

    stats_o<<<OO / 32, 1024>>>(p, a, s);
    stats_x<<<NN / 8, 256>>>(x);
    cudaFuncSetAttribute(mobius_main, cudaFuncAttributeMaxDynamicSharedMemorySize,
                         SMEM_BYTES);
    dim3 grid(OO / BN, NN / BM);
    mobius_main<<<grid, 256, SMEM_BYTES>>>(x, p, a, out);
}

// round 5
// speedup vs baseline: 7.6265x; 1.9408x over previous
#include <cuda_runtime.h>
#include <cuda_fp16.h>
#include <math.h>
#include <cstdint>

#define NN 16384
#define DD 512
#define OO 512
#define BM 128
#define BN 128
#define BK 64                  // k-tile in elements (fp16)
#define NKT (DD / BK)          // 8 k-tiles
#define LH 72                  // smem fp16 per row (BK + 8) -> conflict-free frags
#define TILE_H (BM * LH)       // 9216 halfs per matrix tile
#define STAGE_H (3 * TILE_H)   // X + P + A
#define SMEM_BYTES (3 * STAGE_H * 2)  // 165888 B, 3 stages
#define MINN 1e-15f

// Precomputed stats + fp16 operand copies (no allocations -> device globals).
__device__ float g_a0[NN];    // 1 + ||x||^2
__device__ float g_rr[NN];    // 2 / (1 - ||x||^2)
__device__ float g_B[OO];     // 1 - ||p||^2   (fp64-accurate)
__device__ float g_pa[OO];    // <p, a>
__device__ float g_q[OO];     // 1 / (B * ||a||)
__device__ float g_e2[OO];    // ln(2) * exp(scale)
__device__ __half g_Xh[NN * DD];
__device__ __half g_Ph[OO * DD];
__device__ __half g_Ah[OO * DD];

__device__ __forceinline__ float warp_sum(float v) {
#pragma unroll
    for (int s = 16; s > 0; s >>= 1) v += __shfl_xor_sync(0xffffffffu, v, s);
    return v;
}
__device__ __forceinline__ double warp_sum_d(double v) {
#pragma unroll
    for (int s = 16; s > 0; s >>= 1) v += __shfl_xor_sync(0xffffffffu, v, s);
    return v;
}
__device__ __forceinline__ uint2 cvt4(float4 v) {
    __half2 h0 = __floats2half2_rn(v.x, v.y);
    __half2 h1 = __floats2half2_rn(v.z, v.w);
    uint2 u;
    u.x = *reinterpret_cast<uint32_t*>(&h0);
    u.y = *reinterpret_cast<uint32_t*>(&h1);
    return u;
}

// ---------------- per-O stats + fp16 convert of P, A ----------------
// grid 128, block 128: warp w handles column o = blockIdx*4 + w
__global__ void stats_o(const float* __restrict__ P, const float* __restrict__ A,
                        const float* __restrict__ S) {
    int w = threadIdx.x >> 5, lane = threadIdx.x & 31;
    int o = blockIdx.x * 4 + w;
    const float4* p4 = reinterpret_cast<const float4*>(P + (size_t)o * DD);
    const float4* a4 = reinterpret_cast<const float4*>(A + (size_t)o * DD);
    uint2* ph = reinterpret_cast<uint2*>(g_Ph + (size_t)o * DD);
    uint2* ah = reinterpret_cast<uint2*>(g_Ah + (size_t)o * DD);
    double p2 = 0.0;
    float pa = 0.f, a2 = 0.f;
#pragma unroll
    for (int j = 0; j < 4; j++) {
        int idx = lane + 32 * j;
        float4 pv = p4[idx];
        float4 av = a4[idx];
        ph[idx] = cvt4(pv);
        ah[idx] = cvt4(av);
        p2 += (double)pv.x * pv.x + (double)pv.y * pv.y +
              (double)pv.z * pv.z + (double)pv.w * pv.w;
        pa += pv.x * av.x + pv.y * av.y + pv.z * av.z + pv.w * av.w;
        a2 += av.x * av.x + av.y * av.y + av.z * av.z + av.w * av.w;
    }
    p2 = warp_sum_d(p2);
    pa = warp_sum(pa);
    a2 = warp_sum(a2);
    if (lane == 0) {
        double B = 1.0 - p2;   // catastrophic cancellation handled in fp64
        double an = sqrt((double)a2);
        if (an < (double)MINN) an = (double)MINN;
        g_B[o] = (float)B;
        g_pa[o] = pa;
        g_q[o] = (float)(1.0 / (B * an));
        g_e2[o] = 0.69314718055994530942f * expf(S[o]);
    }
}

// ---------------- per-row ||x||^2 + fp16 convert of X ----------------
__global__ void convert_x(const float* __restrict__ X) {
    int row = (blockIdx.x * blockDim.x + threadIdx.x) >> 5;
    int lane = threadIdx.x & 31;
    const float4* x4 = reinterpret_cast<const float4*>(X + (size_t)row * DD);
    uint2* xh = reinterpret_cast<uint2*>(g_Xh + (size_t)row * DD);
    float s = 0.f;
#pragma unroll
    for (int j = 0; j < 4; j++) {
        int idx = lane + 32 * j;
        float4 v = x4[idx];
        xh[idx] = cvt4(v);
        s += v.x * v.x + v.y * v.y + v.z * v.z + v.w * v.w;
    }
    s = warp_sum(s);
    if (lane == 0) {
        g_a0[row] = 1.f + s;
        g_rr[row] = 2.f / (1.f - s);
    }
}

// ---------------- PTX helpers ----------------
#define MMA_F16(d, a, b0, b1)                                                  \
    asm volatile(                                                              \
        "mma.sync.aligned.m16n8k16.row.col.f32.f16.f16.f32 "                   \
        "{%0,%1,%2,%3}, {%4,%5,%6,%7}, {%8,%9}, {%0,%1,%2,%3};"                \
        : "+f"((d)[0]), "+f"((d)[1]), "+f"((d)[2]), "+f"((d)[3])               \
        : "r"((a)[0]), "r"((a)[1]), "r"((a)[2]), "r"((a)[3]), "r"(b0), "r"(b1))

#define CPA16(saddr, gptr)                                                     \
    asm volatile("cp.async.cg.shared.global [%0], [%1], 16;"                   \
                 :: "r"(saddr), "l"(gptr))
#define CPA_COMMIT() asm volatile("cp.async.commit_group;" ::: "memory")
#define CPA_WAIT1() asm volatile("cp.async.wait_group 1;" ::: "memory")

// asinh(arg)*e^s via fast MUFU: asinh t = ln(t+sqrt(t^2+1)) = lg2(.)*ln2
__device__ __forceinline__ float epi(float xp, float xa, float a0, float rr,
                                     float B, float pa, float q, float e2) {
    float Aa = fmaf(-2.f, xp, a0);      // A = 1 + x^2 - 2*xp
    float tn = fmaf(B, xa, -Aa * pa);   // B*xa - A*pa
    float arg = tn * rr * q;            // 2*tn / (B*(1-x^2)*||a||)
    float tt = fabsf(arg);
    float s;
    asm("sqrt.approx.f32 %0, %1;" : "=f"(s) : "f"(fmaf(tt, tt, 1.f)));
    float u = tt + s;
    float r;
    asm("lg2.approx.f32 %0, %1;" : "=f"(r) : "f"(u));
    return copysignf(r * e2, arg);
}

// ---------------- main: fp16 mma.sync dual-GEMM + analytic Mobius epilogue ----
__global__ void __launch_bounds__(256, 1) mobius_main(float* __restrict__ out) {
    extern __shared__ __half smh[];
    int tid = threadIdx.x;
    int lane = tid & 31, wid = tid >> 5;
    int wm = wid & 1, wn = wid >> 1;        // 2 x 4 warp grid, warp tile 64x32
    int m0 = blockIdx.y * BM, n0 = blockIdx.x * BN;

    const __half* Xg = g_Xh + (size_t)m0 * DD;
    const __half* Pg = g_Ph + (size_t)n0 * DD;
    const __half* Ag = g_Ah + (size_t)n0 * DD;
    uint32_t sbase = (uint32_t)__cvta_generic_to_shared(smh);

    // cp.async mapping: 4 x 16B per matrix per stage per thread
    int f_row[4], f_c16[4];
#pragma unroll
    for (int j = 0; j < 4; j++) {
        int f = tid + 256 * j;          // 0..1023 chunks of 16B
        f_row[j] = f >> 3;
        f_c16[j] = f & 7;
    }

#define LOAD_STAGE(stg, kt)                                                    \
    {                                                                          \
        uint32_t st = sbase + (uint32_t)(stg) * (STAGE_H * 2);                 \
        int k0 = (kt) * BK;                                                    \
        _Pragma("unroll") for (int j = 0; j < 4; j++) {                        \
            uint32_t so = st + (uint32_t)(f_row[j] * LH * 2 + f_c16[j] * 16);  \
            size_t go = (size_t)f_row[j] * DD + k0 + f_c16[j] * 8;             \
            CPA16(so, Xg + go);                                                \
            CPA16(so + TILE_H * 2, Pg + go);                                   \
            CPA16(so + 2 * TILE_H * 2, Ag + go);                               \
        }                                                                      \
    }

    float accP[4][4][4];
    float accA[4][4][4];
#pragma unroll
    for (int mt = 0; mt < 4; mt++)
#pragma unroll
        for (int nt = 0; nt < 4; nt++)
#pragma unroll
            for (int e = 0; e < 4; e++) { accP[mt][nt][e] = 0.f; accA[mt][nt][e] = 0.f; }

    LOAD_STAGE(0, 0); CPA_COMMIT();
    LOAD_STAGE(1, 1); CPA_COMMIT();

    int g = lane >> 2, t = lane & 3;
    // fragment base offsets (halfs) within a stage
    int x_off = (wm * 64 + g) * LH + 2 * t;   // A-frag base (x tile)
    int b_off = (wn * 32 + g) * LH + 2 * t;   // B-frag base (p/a tiles)

    for (int c = 0; c < NKT; ++c) {
        CPA_WAIT1();
        __syncthreads();
        if (c + 2 < NKT) { LOAD_STAGE((c + 2) % 3, c + 2); }
        CPA_COMMIT();

        const __half* Xs = smh + (c % 3) * STAGE_H;
        const __half* Ps = Xs + TILE_H;
        const __half* As = Ps + TILE_H;
#pragma unroll
        for (int ks = 0; ks < 4; ks++) {    // 4 x k16 per k-tile of 64
            uint32_t af[4][4];
#pragma unroll
            for (int mt = 0; mt < 4; mt++) {
                const __half* xb = Xs + x_off + mt * 16 * LH + ks * 16;
                af[mt][0] = *reinterpret_cast<const uint32_t*>(xb);
                af[mt][1] = *reinterpret_cast<const uint32_t*>(xb + 8 * LH);
                af[mt][2] = *reinterpret_cast<const uint32_t*>(xb + 8);
                af[mt][3] = *reinterpret_cast<const uint32_t*>(xb + 8 * LH + 8);
            }
#pragma unroll
            for (int nt = 0; nt < 4; nt++) {
                const __half* pb = Ps + b_off + nt * 8 * LH + ks * 16;
                const __half* ab = As + b_off + nt * 8 * LH + ks * 16;
                uint32_t bp0 = *reinterpret_cast<const uint32_t*>(pb);
                uint32_t bp1 = *reinterpret_cast<const uint32_t*>(pb + 8);
                uint32_t ba0 = *reinterpret_cast<const uint32_t*>(ab);
                uint32_t ba1 = *reinterpret_cast<const uint32_t*>(ab + 8);
#pragma unroll
                for (int mt = 0; mt < 4; mt++) {
                    MMA_F16(accP[mt][nt], af[mt], bp0, bp1);
                    MMA_F16(accA[mt][nt], af[mt], ba0, ba1);
                }
            }
        }
    }

    // ---- epilogue ----
    float a0r[4][2], rrr[4][2];
#pragma unroll
    for (int mt = 0; mt < 4; mt++)
#pragma unroll
        for (int h = 0; h < 2; h++) {
            int r = m0 + wm * 64 + mt * 16 + g + h * 8;
            a0r[mt][h] = g_a0[r];
            rrr[mt][h] = g_rr[r];
        }
    float Bc[4][2], pac[4][2], qc[4][2], e2c[4][2];
#pragma unroll
    for (int nt = 0; nt < 4; nt++)
#pragma unroll
        for (int w = 0; w < 2; w++) {
            int cc = n0 + wn * 32 + nt * 8 + 2 * t + w;
            Bc[nt][w] = g_B[cc];
            pac[nt][w] = g_pa[cc];
            qc[nt][w] = g_q[cc];
            e2c[nt][w] = g_e2[cc];
        }
#pragma unroll
    for (int mt = 0; mt < 4; mt++) {
#pragma unroll
        for (int h = 0; h < 2; h++) {
            int r = m0 + wm * 64 + mt * 16 + g + h * 8;
            float* orow = out + (size_t)r * OO + n0 + wn * 32 + 2 * t;
#pragma unroll
            for (int nt = 0; nt < 4; nt++) {
                float o0 = epi(accP[mt][nt][h * 2 + 0], accA[mt][nt][h * 2 + 0],
                               a0r[mt][h], rrr[mt][h],
                               Bc[nt][0], pac[nt][0], qc[nt][0], e2c[nt][0]);
                float o1 = epi(accP[mt][nt][h * 2 + 1], accA[mt][nt][h * 2 + 1],
                               a0r[mt][h], rrr[mt][h],
                               Bc[nt][1], pac[nt][1], qc[nt][1], e2c[nt][1]);
                *reinterpret_cast<float2*>(orow + nt * 8) = make_float2(o0, o1);
            }
        }
    }
}

extern "C" void kernel_launch(void* const* d_in, const int* in_sizes, int n_in,
                              void* d_out, int out_size) {
    const float* x = (const float*)d_in[0];      // [N, D]
    const float* p = (const float*)d_in[1];      // [O, D]
    const float* a = (const float*)d_in[2];      // [O, D]
    const float* s = (const float*)d_in[3];      // [O]
    float* out = (float*)d_out;                  // [N, O]

    stats_o<<<OO / 4, 128>>>(p, a, s);
    convert_x<<<NN / 8, 256>>>(x);
    cudaFuncSetAttribute(mobius_main, cudaFuncAttributeMaxDynamicSharedMemorySize,
                         SMEM_BYTES);
    dim3 grid(OO / BN, NN / BM);
    mobius_main<<<grid, 256, SMEM_BYTES>>>(out);
}

// round 6
// speedup vs baseline: 8.7084x; 1.1418x over previous
#include <cuda_runtime.h>
#include <cuda_fp16.h>
#include <math.h>
#include <cstdint>

#define NN 16384
#define DD 512
#define OO 512
#define BM 128
#define BN 64
#define BK 64                   // k-tile in elements (fp16)
#define NKT (DD / BK)           // 8 k-tiles
#define LH 72                   // smem fp16 per row (BK + 8) -> conflict-free frags
#define TXH (BM * LH)           // 9216 halfs, X tile
#define TBH (BN * LH)           // 4608 halfs, P or A tile
#define STAGE_H (TXH + 2 * TBH) // 18432 halfs
#define SMEM_BYTES (3 * STAGE_H * 2)  // 110592 B, 3 stages
#define MINN 1e-15f

// Precomputed stats + fp16 operand copies (no allocations -> device globals).
__device__ float g_a0[NN];    // 1 + ||x||^2
__device__ float g_rr[NN];    // 2 / (1 - ||x||^2)
__device__ float g_B[OO];     // 1 - ||p||^2   (fp64-accurate)
__device__ float g_pa[OO];    // <p, a>
__device__ float g_q[OO];     // 1 / (B * ||a||)
__device__ float g_e2[OO];    // ln(2) * exp(scale)
__device__ __half g_Xh[NN * DD];
__device__ __half g_Ph[OO * DD];
__device__ __half g_Ah[OO * DD];

__device__ __forceinline__ float warp_sum(float v) {
#pragma unroll
    for (int s = 16; s > 0; s >>= 1) v += __shfl_xor_sync(0xffffffffu, v, s);
    return v;
}
__device__ __forceinline__ double warp_sum_d(double v) {
#pragma unroll
    for (int s = 16; s > 0; s >>= 1) v += __shfl_xor_sync(0xffffffffu, v, s);
    return v;
}
__device__ __forceinline__ uint2 cvt4(float4 v) {
    __half2 h0 = __floats2half2_rn(v.x, v.y);
    __half2 h1 = __floats2half2_rn(v.z, v.w);
    uint2 u;
    u.x = *reinterpret_cast<uint32_t*>(&h0);
    u.y = *reinterpret_cast<uint32_t*>(&h1);
    return u;
}

// ---------------- fused prep: X convert + x-stats | P/A convert + o-stats ----
// blocks [0, 2048): convert 8 X rows (warp per row) + ||x||^2 stats
// blocks [2048, 2560): one block per o: convert P/A row + column stats
__global__ void prep(const float* __restrict__ X, const float* __restrict__ P,
                     const float* __restrict__ A, const float* __restrict__ S) {
    int bid = blockIdx.x;
    int tid = threadIdx.x;
    int wid = tid >> 5, lane = tid & 31;
    if (bid < 2048) {
        int row = bid * 8 + wid;
        const float4* x4 = reinterpret_cast<const float4*>(X + (size_t)row * DD);
        uint2* xh = reinterpret_cast<uint2*>(g_Xh + (size_t)row * DD);
        float s = 0.f;
#pragma unroll
        for (int j = 0; j < 4; j++) {
            int idx = lane + 32 * j;
            float4 v = x4[idx];
            xh[idx] = cvt4(v);
            s += v.x * v.x + v.y * v.y + v.z * v.z + v.w * v.w;
        }
        s = warp_sum(s);
        if (lane == 0) {
            g_a0[row] = 1.f + s;
            g_rr[row] = 2.f / (1.f - s);
        }
    } else {
        int o = bid - 2048;
        __shared__ double sp2[4];
        __shared__ float spa[4], sa2[4];
        double p2 = 0.0;
        float pa = 0.f, a2 = 0.f;
        if (tid < 128) {
            const float4* p4 = reinterpret_cast<const float4*>(P + (size_t)o * DD);
            const float4* a4 = reinterpret_cast<const float4*>(A + (size_t)o * DD);
            uint2* ph = reinterpret_cast<uint2*>(g_Ph + (size_t)o * DD);
            uint2* ah = reinterpret_cast<uint2*>(g_Ah + (size_t)o * DD);
            float4 pv = p4[tid];
            float4 av = a4[tid];
            ph[tid] = cvt4(pv);
            ah[tid] = cvt4(av);
            p2 = (double)pv.x * pv.x + (double)pv.y * pv.y +
                 (double)pv.z * pv.z + (double)pv.w * pv.w;
            pa = pv.x * av.x + pv.y * av.y + pv.z * av.z + pv.w * av.w;
            a2 = av.x * av.x + av.y * av.y + av.z * av.z + av.w * av.w;
            p2 = warp_sum_d(p2);
            pa = warp_sum(pa);
            a2 = warp_sum(a2);
            if (lane == 0) { sp2[wid] = p2; spa[wid] = pa; sa2[wid] = a2; }
        }
        __syncthreads();
        if (tid == 0) {
            double tp2 = sp2[0] + sp2[1] + sp2[2] + sp2[3];
            float tpa = spa[0] + spa[1] + spa[2] + spa[3];
            float ta2 = sa2[0] + sa2[1] + sa2[2] + sa2[3];
            double B = 1.0 - tp2;    // catastrophic cancellation handled in fp64
            double an = sqrt((double)ta2);
            if (an < (double)MINN) an = (double)MINN;
            g_B[o] = (float)B;
            g_pa[o] = tpa;
            g_q[o] = (float)(1.0 / (B * an));
            g_e2[o] = 0.69314718055994530942f * expf(S[o]);
        }
    }
}

// ---------------- PTX helpers ----------------
#define MMA_F16(d, a, b0, b1)                                                  \
    asm volatile(                                                              \
        "mma.sync.aligned.m16n8k16.row.col.f32.f16.f16.f32 "                   \
        "{%0,%1,%2,%3}, {%4,%5,%6,%7}, {%8,%9}, {%0,%1,%2,%3};"                \
        : "+f"((d)[0]), "+f"((d)[1]), "+f"((d)[2]), "+f"((d)[3])               \
        : "r"((a)[0]), "r"((a)[1]), "r"((a)[2]), "r"((a)[3]), "r"(b0), "r"(b1))

#define CPA16(saddr, gptr)                                                     \
    asm volatile("cp.async.cg.shared.global [%0], [%1], 16;"                   \
                 :: "r"(saddr), "l"(gptr))
#define CPA_COMMIT() asm volatile("cp.async.commit_group;" ::: "memory")
#define CPA_WAIT1() asm volatile("cp.async.wait_group 1;" ::: "memory")

// asinh(arg)*e^s via fast MUFU: asinh t = ln(t+sqrt(t^2+1)) = lg2(.)*ln2
__device__ __forceinline__ float epi(float xp, float xa, float a0, float rr,
                                     float B, float pa, float q, float e2) {
    float Aa = fmaf(-2.f, xp, a0);      // A = 1 + x^2 - 2*xp
    float tn = fmaf(B, xa, -Aa * pa);   // B*xa - A*pa
    float arg = tn * rr * q;            // 2*tn / (B*(1-x^2)*||a||)
    float tt = fabsf(arg);
    float s;
    asm("sqrt.approx.f32 %0, %1;" : "=f"(s) : "f"(fmaf(tt, tt, 1.f)));
    float u = tt + s;
    float r;
    asm("lg2.approx.f32 %0, %1;" : "=f"(r) : "f"(u));
    return copysignf(r * e2, arg);
}

// ---------------- main: fp16 mma.sync dual-GEMM + analytic Mobius epilogue ----
// 128x64 block tile, 256 threads, warp grid 2(M) x 4(N), warp tile 64x16.
__global__ void __launch_bounds__(256, 2) mobius_main(float* __restrict__ out) {
    extern __shared__ __half smh[];
    int tid = threadIdx.x;
    int lane = tid & 31, wid = tid >> 5;
    int wm = wid & 1, wn = wid >> 1;
    int m0 = blockIdx.y * BM, n0 = blockIdx.x * BN;

    const __half* Xg = g_Xh + (size_t)m0 * DD;
    const __half* Pg = g_Ph + (size_t)n0 * DD;
    const __half* Ag = g_Ah + (size_t)n0 * DD;
    uint32_t sbase = (uint32_t)__cvta_generic_to_shared(smh);

#define LOAD_STAGE(stg, kt)                                                    \
    {                                                                          \
        uint32_t st = sbase + (uint32_t)(stg) * (STAGE_H * 2);                 \
        int k0 = (kt) * BK;                                                    \
        _Pragma("unroll") for (int j = 0; j < 4; j++) {  /* X: 1024 chunks */  \
            int f = tid + 256 * j;                                             \
            int row = f >> 3, ck = f & 7;                                      \
            CPA16(st + (uint32_t)(row * (LH * 2) + ck * 16),                   \
                  Xg + (size_t)row * DD + k0 + ck * 8);                        \
        }                                                                      \
        _Pragma("unroll") for (int j = 0; j < 2; j++) {  /* P: 512 chunks */   \
            int f = tid + 256 * j;                                             \
            int row = f >> 3, ck = f & 7;                                      \
            CPA16(st + (uint32_t)(TXH * 2 + row * (LH * 2) + ck * 16),         \
                  Pg + (size_t)row * DD + k0 + ck * 8);                        \
        }                                                                      \
        _Pragma("unroll") for (int j = 0; j < 2; j++) {  /* A: 512 chunks */   \
            int f = tid + 256 * j;                                             \
            int row = f >> 3, ck = f & 7;                                      \
            CPA16(st + (uint32_t)((TXH + TBH) * 2 + row * (LH * 2) + ck * 16), \
                  Ag + (size_t)row * DD + k0 + ck * 8);                        \
        }                                                                      \
    }

    float accP[4][2][4];
    float accA[4][2][4];
#pragma unroll
    for (int mt = 0; mt < 4; mt++)
#pragma unroll
        for (int nt = 0; nt < 2; nt++)
#pragma unroll
            for (int e = 0; e < 4; e++) { accP[mt][nt][e] = 0.f; accA[mt][nt][e] = 0.f; }

    LOAD_STAGE(0, 0); CPA_COMMIT();
    LOAD_STAGE(1, 1); CPA_COMMIT();

    int g = lane >> 2, t = lane & 3;
    int x_off = (wm * 64 + g) * LH + 2 * t;   // A-frag base (x tile)
    int b_off = (wn * 16 + g) * LH + 2 * t;   // B-frag base (p/a tiles)

    for (int c = 0; c < NKT; ++c) {
        CPA_WAIT1();
        __syncthreads();
        if (c + 2 < NKT) { LOAD_STAGE((c + 2) % 3, c + 2); }
        CPA_COMMIT();

        const __half* Xs = smh + (c % 3) * STAGE_H;
        const __half* Ps = Xs + TXH;
        const __half* As = Ps + TBH;
#pragma unroll
        for (int ks = 0; ks < 4; ks++) {    // 4 x k16 per k-tile of 64
            uint32_t af[4][4];
#pragma unroll
            for (int mt = 0; mt < 4; mt++) {
                const __half* xb = Xs + x_off + mt * 16 * LH + ks * 16;
                af[mt][0] = *reinterpret_cast<const uint32_t*>(xb);
                af[mt][1] = *reinterpret_cast<const uint32_t*>(xb + 8 * LH);
                af[mt][2] = *reinterpret_cast<const uint32_t*>(xb + 8);
                af[mt][3] = *reinterpret_cast<const uint32_t*>(xb + 8 * LH + 8);
            }
#pragma unroll
            for (int nt = 0; nt < 2; nt++) {
                const __half* pb = Ps + b_off + nt * 8 * LH + ks * 16;
                const __half* ab = As + b_off + nt * 8 * LH + ks * 16;
                uint32_t bp0 = *reinterpret_cast<const uint32_t*>(pb);
                uint32_t bp1 = *reinterpret_cast<const uint32_t*>(pb + 8);
                uint32_t ba0 = *reinterpret_cast<const uint32_t*>(ab);
                uint32_t ba1 = *reinterpret_cast<const uint32_t*>(ab + 8);
#pragma unroll
                for (int mt = 0; mt < 4; mt++) {
                    MMA_F16(accP[mt][nt], af[mt], bp0, bp1);
                    MMA_F16(accA[mt][nt], af[mt], ba0, ba1);
                }
            }
        }
    }

    // ---- epilogue ----
    float a0r[4][2], rrr[4][2];
#pragma unroll
    for (int mt = 0; mt < 4; mt++)
#pragma unroll
        for (int h = 0; h < 2; h++) {
            int r = m0 + wm * 64 + mt * 16 + g + h * 8;
            a0r[mt][h] = g_a0[r];
            rrr[mt][h] = g_rr[r];
        }
    float Bc[2][2], pac[2][2], qc[2][2], e2c[2][2];
#pragma unroll
    for (int nt = 0; nt < 2; nt++)
#pragma unroll
        for (int w = 0; w < 2; w++) {
            int cc = n0 + wn * 16 + nt * 8 + 2 * t + w;
            Bc[nt][w] = g_B[cc];
            pac[nt][w] = g_pa[cc];
            qc[nt][w] = g_q[cc];
            e2c[nt][w] = g_e2[cc];
        }
#pragma unroll
    for (int mt = 0; mt < 4; mt++) {
#pragma unroll
        for (int h = 0; h < 2; h++) {
            int r = m0 + wm * 64 + mt * 16 + g + h * 8;
            float* orow = out + (size_t)r * OO + n0 + wn * 16 + 2 * t;
#pragma unroll
            for (int nt = 0; nt < 2; nt++) {
                float o0 = epi(accP[mt][nt][h * 2 + 0], accA[mt][nt][h * 2 + 0],
                               a0r[mt][h], rrr[mt][h],
                               Bc[nt][0], pac[nt][0], qc[nt][0], e2c[nt][0]);
                float o1 = epi(accP[mt][nt][h * 2 + 1], accA[mt][nt][h * 2 + 1],
                               a0r[mt][h], rrr[mt][h],
                               Bc[nt][1], pac[nt][1], qc[nt][1], e2c[nt][1]);
                *reinterpret_cast<float2*>(orow + nt * 8) = make_float2(o0, o1);
            }
        }
    }
}

extern "C" void kernel_launch(void* const* d_in, const int* in_sizes, int n_in,
                              void* d_out, int out_size) {
    const float* x = (const float*)d_in[0];      // [N, D]
    const float* p = (const float*)d_in[1];      // [O, D]
    const float* a = (const float*)d_in[2];      // [O, D]
    const float* s = (const float*)d_in[3];      // [O]
    float* out = (float*)d_out;                  // [N, O]

    prep<<<2048 + OO, 256>>>(x, p, a, s);
    cudaFuncSetAttribute(mobius_main, cudaFuncAttributeMaxDynamicSharedMemorySize,
                         SMEM_BYTES);
    dim3 grid(OO / BN, NN / BM);
    mobius_main<<<grid, 256, SMEM_BYTES>>>(out);
}